// round 11
// baseline (speedup 1.0000x reference)
#include <cuda_runtime.h>
#include <cuda_fp16.h>
#include <cstdint>

// ---------------- problem constants ----------------
#define NT     4096          // B*T tokens
#define TTT    2048          // T per batch
#define DMODEL 1024
#define INNER  2048
#define DSTATE 64
#define NHID   4096
#define NEXP   4
#define NDTBC  256           // padded dt|B|C projection width (192 -> 256)

// ---------------- device scratch ----------------
__device__ __half g_x1h[(size_t)NT * DMODEL];
__device__ float  g_xz[(size_t)NT * 4096];
__device__ float  g_xmain[(size_t)NT * INNER];
__device__ __half g_xmainh[(size_t)NT * INNER];
__device__ __half g_wdtbcH[(size_t)NDTBC * INNER];   // [N=256, K=2048] fp16
__device__ float  g_bdtbc[NDTBC];
__device__ float  g_dtBC[(size_t)NT * NDTBC];
__device__ float  g_y[(size_t)NT * DSTATE];
__device__ __half g_yh[(size_t)NT * DSTATE];
__device__ float  g_yin[(size_t)NT * INNER];
__device__ __half g_yinh[(size_t)NT * INNER];
__device__ float  g_xmid[(size_t)NT * DMODEL];
__device__ float  g_x2[(size_t)NT * DMODEL];
__device__ __half g_x2h[(size_t)NT * DMODEL];
__device__ __half g_hidh[(size_t)NT * NHID];
__device__ int    g_cnt[NEXP];
__device__ int    g_idx[NEXP * NT];
__device__ float  g_wtok[NEXP * NT];
// fp16 transposed weights [N, K]
__device__ __half g_winT[(size_t)4096 * DMODEL];
__device__ __half g_woutT[(size_t)DMODEL * INNER];
__device__ __half g_s2iT[(size_t)INNER * DSTATE];
__device__ __half g_we1T[(size_t)NEXP * NHID * DMODEL];
__device__ __half g_we2T[(size_t)NEXP * DMODEL * NHID];

#define MMA_F16(d, a, b)                                                     \
    asm volatile("mma.sync.aligned.m16n8k16.row.col.f32.f16.f16.f32 "        \
                 "{%0,%1,%2,%3},{%4,%5,%6,%7},{%8,%9},{%0,%1,%2,%3};"        \
                 : "+f"(d[0]), "+f"(d[1]), "+f"(d[2]), "+f"(d[3])            \
                 : "r"(a[0]), "r"(a[1]), "r"(a[2]), "r"(a[3]),               \
                   "r"(b[0]), "r"(b[1]))

#define LDSM4(r0, r1, r2, r3, a)                                             \
    asm volatile("ldmatrix.sync.aligned.m8n8.x4.shared.b16 {%0,%1,%2,%3}, [%4];" \
                 : "=r"(r0), "=r"(r1), "=r"(r2), "=r"(r3) : "r"(a))

__device__ __forceinline__ uint32_t smem_u32(const void* p) {
    uint32_t a;
    asm("{ .reg .u64 t; cvta.to.shared.u64 t, %1; cvt.u32.u64 %0, t; }" : "=r"(a) : "l"(p));
    return a;
}

#define AP 12   // u32 pitch per 128-row tile row (8 u32 payload + 4 pad)

// ============ fp16 tensor-core GEMM: A[M,K] half, Bt[N,K] half =============
// epi: 0 = out = acc + bias
//      2 = out = gelu(acc + bias)          (exact erf)
//      3 = out = resid + acc + bias        (fp32 C only)
//      4 = moe_out[out_idx[r]] += wrow[r] * (acc + bias)
// Output: C (fp32) if Ch == null, else Ch (fp16).
// Requires: K % 16 == 0, N % 128 == 0.
__global__ __launch_bounds__(256, 2)
void hgemm_kernel(const __half* __restrict__ A, const __half* __restrict__ Bt,
                  const float* __restrict__ bias, float* __restrict__ C,
                  __half* __restrict__ Ch,
                  int M, int N, int K,
                  const int* __restrict__ a_idx, const int* __restrict__ Mdev,
                  int epi, const float* __restrict__ resid,
                  const int* __restrict__ out_idx, const float* __restrict__ wrow,
                  float* __restrict__ moe_out)
{
    if (Mdev) M = *Mdev;
    const int tileM = blockIdx.y * 128;
    const int tileN = blockIdx.x * 128;
    if (tileM >= M) return;

    __shared__ uint32_t As[2][128 * AP];
    __shared__ uint32_t Bs[2][128 * AP];

    const int tid  = threadIdx.x;
    const int lane = tid & 31;
    const int wid  = tid >> 5;
    const int wm   = wid >> 2;       // 0..1  (64-row band)
    const int wn   = wid & 3;        // 0..3  (32-col band)
    const int g    = lane >> 2;      // 0..7
    const int th   = lane & 3;       // 0..3

    // ---- staging assignments (identical pattern for A and B) ----
    const int s_row = tid >> 1;          // 0..127
    const int s_kh  = (tid & 1);         // half-row: 8 halves each
    const __half* a_ptr = nullptr;
    {
        int ar = tileM + s_row;
        if (ar < M) {
            int gi = a_idx ? a_idx[ar] : ar;
            a_ptr = A + (size_t)gi * K + s_kh * 8;
        }
    }
    const __half* b_ptr = Bt + (size_t)(tileN + s_row) * K + s_kh * 8;
    const uint32_t s_off = (uint32_t)(s_row * AP + s_kh * 4);

    // ---- ldmatrix per-lane offsets (u32 units) ----
    const uint32_t aoff = (uint32_t)(((lane & 7) + 8 * ((lane >> 3) & 1)) * AP + 4 * (lane >> 4));
    const uint32_t boff = (uint32_t)(((lane & 7) + 8 * (lane >> 4)) * AP + 4 * ((lane >> 3) & 1));
    const uint32_t As_base[2] = { smem_u32(&As[0][0]), smem_u32(&As[1][0]) };
    const uint32_t Bs_base[2] = { smem_u32(&Bs[0][0]), smem_u32(&Bs[1][0]) };

    float acc[4][4][4];
#pragma unroll
    for (int mt = 0; mt < 4; mt++)
#pragma unroll
        for (int nt = 0; nt < 4; nt++)
#pragma unroll
            for (int r = 0; r < 4; r++) acc[mt][nt][r] = 0.f;

    uint4 av = make_uint4(0u, 0u, 0u, 0u), bv;
    if (a_ptr) av = *(const uint4*)(a_ptr);
    bv = *(const uint4*)(b_ptr);
    *(uint4*)&As[0][s_off] = av;
    *(uint4*)&Bs[0][s_off] = bv;
    __syncthreads();

    const int KT = K >> 4;
    for (int kt = 0; kt < KT; kt++) {
        const int p = kt & 1;
        if (kt + 1 < KT) {       // prefetch next K-tile into regs
            const int k0 = (kt + 1) << 4;
            if (a_ptr) av = *(const uint4*)(a_ptr + k0);
            bv = *(const uint4*)(b_ptr + k0);
        }

        // ---- compute from stage p ----
        {
            uint32_t afr[4][4], bfr[4][2];
#pragma unroll
            for (int mt = 0; mt < 4; mt++) {
                const uint32_t addr = As_base[p] + ((uint32_t)((wm * 64 + mt * 16) * AP) + aoff) * 4u;
                LDSM4(afr[mt][0], afr[mt][1], afr[mt][2], afr[mt][3], addr);
            }
#pragma unroll
            for (int p2 = 0; p2 < 2; p2++) {
                const uint32_t addr = Bs_base[p] + ((uint32_t)((wn * 32 + p2 * 16) * AP) + boff) * 4u;
                LDSM4(bfr[2 * p2][0], bfr[2 * p2][1], bfr[2 * p2 + 1][0], bfr[2 * p2 + 1][1], addr);
            }
#pragma unroll
            for (int mt = 0; mt < 4; mt++)
#pragma unroll
                for (int nt = 0; nt < 4; nt++)
                    MMA_F16(acc[mt][nt], afr[mt], bfr[nt]);
        }

        if (kt + 1 < KT) {       // store next stage
            const int q = p ^ 1;
            *(uint4*)&As[q][s_off] = av;
            *(uint4*)&Bs[q][s_off] = bv;
        }
        __syncthreads();
    }

    // ---- epilogue ----
#pragma unroll
    for (int mt = 0; mt < 4; mt++) {
        const int rbase = tileM + wm * 64 + mt * 16 + g;
#pragma unroll
        for (int h = 0; h < 2; h++) {
            const int r = rbase + h * 8;
            if (r >= M) continue;
            int   orow = r;
            float wr   = 1.f;
            if (epi == 4) { orow = out_idx[r]; wr = wrow[r]; }
#pragma unroll
            for (int nt = 0; nt < 4; nt++) {
                const int c = tileN + wn * 32 + nt * 8 + 2 * th;
                float v0 = acc[mt][nt][h * 2 + 0] + bias[c];
                float v1 = acc[mt][nt][h * 2 + 1] + bias[c + 1];
                if (epi == 2) {
                    v0 = 0.5f * v0 * (1.f + erff(v0 * 0.70710678118654752f));
                    v1 = 0.5f * v1 * (1.f + erff(v1 * 0.70710678118654752f));
                }
                if (epi == 3) {
                    v0 += resid[(size_t)r * N + c];
                    v1 += resid[(size_t)r * N + c + 1];
                }
                if (epi == 4) {
                    float* p2 = moe_out + (size_t)orow * N + c;
                    p2[0] += wr * v0;
                    p2[1] += wr * v1;
                } else if (Ch) {
                    __half2 hv = __floats2half2_rn(v0, v1);
                    *(__half2*)(Ch + (size_t)r * N + c) = hv;
                } else {
                    C[(size_t)r * N + c]     = v0;
                    C[(size_t)r * N + c + 1] = v1;
                }
            }
        }
    }
}

// ---------------- weight transpose+convert: W[K,N] f32 -> Wt[N,K] f16 ------
__global__ void wT_kernel(const float* __restrict__ W, __half* __restrict__ Wt,
                          int K, int N)
{
    __shared__ float t[32][33];
    const int n0 = blockIdx.x * 32, k0 = blockIdx.y * 32;
    const int x = threadIdx.x, y = threadIdx.y;
#pragma unroll
    for (int j = 0; j < 32; j += 8)
        t[y + j][x] = W[(size_t)(k0 + y + j) * N + n0 + x];
    __syncthreads();
#pragma unroll
    for (int j = 0; j < 32; j += 8)
        Wt[(size_t)(n0 + y + j) * K + k0 + x] = __float2half(t[x][y + j]);
}

// ---------------- RMSNorm: optional fp32 out, fp16 out, raw copy ----------
__global__ void rmsnorm_kernel(const float* __restrict__ in,
                               const float* __restrict__ w,
                               float* __restrict__ out,
                               __half* __restrict__ out_h,
                               float* __restrict__ copy_dst)
{
    const int tok = blockIdx.x;
    const float* row = in + (size_t)tok * DMODEL;
    float s = 0.f;
    for (int i = threadIdx.x; i < DMODEL; i += 256) { float v = row[i]; s = fmaf(v, v, s); }
    __shared__ float red[8];
    for (int off = 16; off; off >>= 1) s += __shfl_xor_sync(0xffffffffu, s, off);
    if ((threadIdx.x & 31) == 0) red[threadIdx.x >> 5] = s;
    __syncthreads();
    if (threadIdx.x < 32) {
        float tv = (threadIdx.x < 8) ? red[threadIdx.x] : 0.f;
        for (int off = 4; off; off >>= 1) tv += __shfl_xor_sync(0xffffffffu, tv, off);
        if (threadIdx.x == 0) red[0] = tv;
    }
    __syncthreads();
    const float nr = rsqrtf(red[0] * (1.f / DMODEL) + 1e-6f);
    for (int i = threadIdx.x; i < DMODEL; i += 256) {
        float v = row[i];
        float o = v * nr * w[i];
        if (out)   out[(size_t)tok * DMODEL + i] = o;
        if (out_h) out_h[(size_t)tok * DMODEL + i] = __float2half(o);
        if (copy_dst) copy_dst[(size_t)tok * DMODEL + i] = v;
    }
}

// -------- causal depthwise conv (K=3) + bias + SiLU -> fp32 and fp16 -------
__global__ void conv_silu_kernel(const float* __restrict__ xz,
                                 const float* __restrict__ cw,
                                 const float* __restrict__ cb,
                                 float* __restrict__ xmain,
                                 __half* __restrict__ xmainh)
{
    const int i = blockIdx.x * 256 + threadIdx.x;   // NT*INNER threads
    const int c   = i & (INNER - 1);
    const int tok = i >> 11;
    const int t   = tok & (TTT - 1);
    const float w0 = cw[c * 3 + 0], w1 = cw[c * 3 + 1], w2 = cw[c * 3 + 2];
    float v = cb[c];
    float xm2 = (t >= 2) ? xz[(size_t)(tok - 2) * 4096 + c] : 0.f;
    float xm1 = (t >= 1) ? xz[(size_t)(tok - 1) * 4096 + c] : 0.f;
    float xm0 = xz[(size_t)tok * 4096 + c];
    v = fmaf(w0, xm2, fmaf(w1, xm1, fmaf(w2, xm0, v)));
    float o = v / (1.f + expf(-v));   // silu
    xmain[i]  = o;
    xmainh[i] = __float2half(o);
}

// ------- pack dt_w|bp_w|cp_w into fp16 Bt [256, 2048] (+fp32 biases) -------
__global__ void pack_dtbc_kernel(const float* __restrict__ dtw, const float* __restrict__ bpw,
                                 const float* __restrict__ cpw, const float* __restrict__ dtb,
                                 const float* __restrict__ bpb, const float* __restrict__ cpb)
{
    const int i = blockIdx.x * 256 + threadIdx.x;   // NDTBC * INNER threads
    const int n = i >> 11;          // 0..255
    const int k = i & (INNER - 1);
    float v = 0.f;
    if (n < 192) {
        int sel = n >> 6, cc = n & 63;
        const float* w = (sel == 0) ? dtw : (sel == 1) ? bpw : cpw;
        v = w[k * 64 + cc];
    }
    g_wdtbcH[i] = __float2half(v);
    if (i < NDTBC) {
        float b = 0.f;
        if (i < 192) {
            int sel = i >> 6, cc = i & 63;
            const float* bp = (sel == 0) ? dtb : (sel == 1) ? bpb : cpb;
            b = bp[cc];
        }
        g_bdtbc[i] = b;
    }
}

// ---------------- selective-state scan (dtBC stride 256) -------------------
__global__ void scan_kernel(const float* __restrict__ dtBC, float* __restrict__ y)
{
    const int warp = blockIdx.x;            // 128 chains, one warp per block
    const int lane = threadIdx.x & 31;
    const int b = warp >> 6, s = warp & 63;
    const int t0 = lane * 64;
    const size_t base = (size_t)b * TTT * NDTBC;

    float A = 1.f, Bc = 0.f;
    for (int t = t0; t < t0 + 64; t++) {
        size_t o = base + (size_t)t * NDTBC;
        float dt = 1.f / (1.f + expf(-dtBC[o + s]));
        float bvv = dtBC[o + 64 + s];
        float a = 1.f - dt;
        Bc = fmaf(a, Bc, dt * bvv);
        A *= a;
    }
    for (int off = 1; off < 32; off <<= 1) {
        float Au = __shfl_up_sync(0xffffffffu, A, off);
        float Bu = __shfl_up_sync(0xffffffffu, Bc, off);
        if (lane >= off) { Bc = fmaf(A, Bu, Bc); A = A * Au; }
    }
    float start = __shfl_up_sync(0xffffffffu, Bc, 1);
    if (lane == 0) start = 0.f;

    float st = start;
    for (int t = t0; t < t0 + 64; t++) {
        size_t o = base + (size_t)t * NDTBC;
        float dt = 1.f / (1.f + expf(-dtBC[o + s]));
        float bvv = dtBC[o + 64 + s];
        float cv = dtBC[o + 128 + s];
        st = fmaf(1.f - dt, st, dt * bvv);
        y[((size_t)b * TTT + t) * 64 + s] = cv * st;
    }
}

// ------- LayerNorm over 64 dims (warp per token) -> fp16 out ---------------
__global__ void ln64_kernel(const float* __restrict__ y, __half* __restrict__ yh)
{
    const int token = blockIdx.x * 8 + (threadIdx.x >> 5);
    const int lane  = threadIdx.x & 31;
    const float* row = y + (size_t)token * 64;
    float a = row[lane], b = row[lane + 32];
    float s = a + b;
    for (int off = 16; off; off >>= 1) s += __shfl_xor_sync(0xffffffffu, s, off);
    float mu = s * (1.f / 64.f);
    float da = a - mu, db = b - mu;
    float v = da * da + db * db;
    for (int off = 16; off; off >>= 1) v += __shfl_xor_sync(0xffffffffu, v, off);
    float inv = rsqrtf(v * (1.f / 64.f) + 1e-5f);
    yh[(size_t)token * 64 + lane]      = __float2half(da * inv);
    yh[(size_t)token * 64 + lane + 32] = __float2half(db * inv);
}

// ---------------- yinh = half((yin + D*xmain) * sigmoid(gate)) -------------
__global__ void skipgate_kernel(const float* __restrict__ yin, const float* __restrict__ xmain,
                                const float* __restrict__ xz, const float* __restrict__ Dp,
                                __half* __restrict__ yinh)
{
    const int i = blockIdx.x * 256 + threadIdx.x;   // NT*INNER
    const int c   = i & (INNER - 1);
    const int tok = i >> 11;
    float g = xz[(size_t)tok * 4096 + INNER + c];
    float v = fmaf(Dp[c], xmain[i], yin[i]);
    yinh[i] = __float2half(v / (1.f + expf(-g)));
}

// ---------------- gating: logits, top-2, softmax, expert compaction --------
__global__ void zero_cnt_kernel() { if (threadIdx.x < NEXP) g_cnt[threadIdx.x] = 0; }

__global__ void gating_kernel(const float* __restrict__ x2, const float* __restrict__ gw,
                              const float* __restrict__ gb)
{
    const int token = blockIdx.x * 8 + (threadIdx.x >> 5);
    const int lane  = threadIdx.x & 31;
    const float* row = x2 + (size_t)token * DMODEL;
    float a0 = 0.f, a1 = 0.f, a2 = 0.f, a3 = 0.f;
    for (int d = lane; d < DMODEL; d += 32) {
        float xv = row[d];
        float4 g = *(const float4*)(gw + d * 4);
        a0 = fmaf(xv, g.x, a0); a1 = fmaf(xv, g.y, a1);
        a2 = fmaf(xv, g.z, a2); a3 = fmaf(xv, g.w, a3);
    }
    for (int off = 16; off; off >>= 1) {
        a0 += __shfl_xor_sync(0xffffffffu, a0, off);
        a1 += __shfl_xor_sync(0xffffffffu, a1, off);
        a2 += __shfl_xor_sync(0xffffffffu, a2, off);
        a3 += __shfl_xor_sync(0xffffffffu, a3, off);
    }
    if (lane == 0) {
        float lg[4] = {a0 + gb[0], a1 + gb[1], a2 + gb[2], a3 + gb[3]};
        int i1 = 0;
        for (int e = 1; e < 4; e++) if (lg[e] > lg[i1]) i1 = e;
        int i2 = -1;
        for (int e = 0; e < 4; e++) if (e != i1 && (i2 < 0 || lg[e] > lg[i2])) i2 = e;
        float t  = expf(lg[i2] - lg[i1]);
        float p1 = 1.f / (1.f + t);
        float p2 = t / (1.f + t);
        int p = atomicAdd(&g_cnt[i1], 1); g_idx[i1 * NT + p] = token; g_wtok[i1 * NT + p] = p1;
        int q = atomicAdd(&g_cnt[i2], 1); g_idx[i2 * NT + q] = token; g_wtok[i2 * NT + q] = p2;
    }
}

// ---------------- host orchestration ----------------
extern "C" void kernel_launch(void* const* d_in, const int* in_sizes, int n_in,
                              void* d_out, int out_size)
{
    const float* x         = (const float*)d_in[0];
    const float* norm1_w   = (const float*)d_in[1];
    const float* norm2_w   = (const float*)d_in[2];
    const float* in_proj_w = (const float*)d_in[3];
    const float* in_proj_b = (const float*)d_in[4];
    const float* conv_w    = (const float*)d_in[5];
    const float* conv_b    = (const float*)d_in[6];
    const float* dt_w      = (const float*)d_in[7];
    const float* dt_b      = (const float*)d_in[8];
    const float* bp_w      = (const float*)d_in[9];
    const float* bp_b      = (const float*)d_in[10];
    const float* cp_w      = (const float*)d_in[11];
    const float* cp_b      = (const float*)d_in[12];
    const float* s2i_w     = (const float*)d_in[13];
    const float* s2i_b     = (const float*)d_in[14];
    const float* D_param   = (const float*)d_in[15];
    const float* out_w     = (const float*)d_in[16];
    const float* out_b     = (const float*)d_in[17];
    const float* gate_w    = (const float*)d_in[18];
    const float* gate_b    = (const float*)d_in[19];
    const float* e_w1      = (const float*)d_in[20];
    const float* e_b1      = (const float*)d_in[21];
    const float* e_w2      = (const float*)d_in[22];
    const float* e_b2      = (const float*)d_in[23];
    float* out = (float*)d_out;

    float *p_xz, *p_xmain, *p_bdtbc, *p_dtBC, *p_y, *p_yin, *p_xmid, *p_x2, *p_wtok;
    __half *p_x1h, *p_xmainh, *p_wdtbcH, *p_yh, *p_yinh, *p_x2h, *p_hidh;
    __half *p_winT, *p_woutT, *p_s2iT, *p_we1T, *p_we2T;
    int *p_cnt, *p_idx;
    cudaGetSymbolAddress((void**)&p_x1h, g_x1h);
    cudaGetSymbolAddress((void**)&p_xz, g_xz);
    cudaGetSymbolAddress((void**)&p_xmain, g_xmain);
    cudaGetSymbolAddress((void**)&p_xmainh, g_xmainh);
    cudaGetSymbolAddress((void**)&p_wdtbcH, g_wdtbcH);
    cudaGetSymbolAddress((void**)&p_bdtbc, g_bdtbc);
    cudaGetSymbolAddress((void**)&p_dtBC, g_dtBC);
    cudaGetSymbolAddress((void**)&p_y, g_y);
    cudaGetSymbolAddress((void**)&p_yh, g_yh);
    cudaGetSymbolAddress((void**)&p_yin, g_yin);
    cudaGetSymbolAddress((void**)&p_yinh, g_yinh);
    cudaGetSymbolAddress((void**)&p_xmid, g_xmid);
    cudaGetSymbolAddress((void**)&p_x2, g_x2);
    cudaGetSymbolAddress((void**)&p_x2h, g_x2h);
    cudaGetSymbolAddress((void**)&p_hidh, g_hidh);
    cudaGetSymbolAddress((void**)&p_cnt, g_cnt);
    cudaGetSymbolAddress((void**)&p_idx, g_idx);
    cudaGetSymbolAddress((void**)&p_wtok, g_wtok);
    cudaGetSymbolAddress((void**)&p_winT, g_winT);
    cudaGetSymbolAddress((void**)&p_woutT, g_woutT);
    cudaGetSymbolAddress((void**)&p_s2iT, g_s2iT);
    cudaGetSymbolAddress((void**)&p_we1T, g_we1T);
    cudaGetSymbolAddress((void**)&p_we2T, g_we2T);

    const dim3 tb(32, 8);

    // --- launches 1..5 (ncu -s 5 skips these; #6 is the big GEMM) ---
    wT_kernel<<<dim3(4096 / 32, DMODEL / 32), tb>>>(in_proj_w, p_winT, DMODEL, 4096);   // 1
    wT_kernel<<<dim3(DMODEL / 32, INNER / 32), tb>>>(out_w, p_woutT, INNER, DMODEL);    // 2
    wT_kernel<<<dim3(INNER / 32, DSTATE / 32), tb>>>(s2i_w, p_s2iT, DSTATE, INNER);     // 3
    rmsnorm_kernel<<<NT, 256>>>(x, norm1_w, nullptr, p_x1h, nullptr);                   // 4
    pack_dtbc_kernel<<<(NDTBC * INNER) / 256, 256>>>(dt_w, bp_w, cp_w, dt_b, bp_b, cp_b); // 5

    // 6) xz = x1 @ in_proj_w + b   [4096 x 4096]  <-- ncu capture target
    hgemm_kernel<<<dim3(32, 32), 256>>>(p_x1h, p_winT, in_proj_b, p_xz, nullptr,
        NT, 4096, DMODEL, nullptr, nullptr, 0, nullptr, nullptr, nullptr, nullptr);

    // remaining weight transposes (needed only for MoE later)
    for (int e = 0; e < NEXP; e++) {
        wT_kernel<<<dim3(NHID / 32, DMODEL / 32), tb>>>(
            e_w1 + (size_t)e * DMODEL * NHID, p_we1T + (size_t)e * NHID * DMODEL, DMODEL, NHID);
        wT_kernel<<<dim3(DMODEL / 32, NHID / 32), tb>>>(
            e_w2 + (size_t)e * NHID * DMODEL, p_we2T + (size_t)e * DMODEL * NHID, NHID, DMODEL);
    }

    // x_main = silu(causal depthwise conv(xz[:, :2048]) + conv_b)
    conv_silu_kernel<<<(NT * INNER) / 256, 256>>>(p_xz, conv_w, conv_b, p_xmain, p_xmainh);

    // packed [dt|B|C] projection (fp16 tensor cores, N padded to 256)
    hgemm_kernel<<<dim3(NDTBC / 128, 32), 256>>>(p_xmainh, p_wdtbcH, p_bdtbc, p_dtBC, nullptr,
        NT, NDTBC, INNER, nullptr, nullptr, 0, nullptr, nullptr, nullptr, nullptr);

    // selective scan + LayerNorm(64) -> fp16
    scan_kernel<<<128, 32>>>(p_dtBC, p_y);
    ln64_kernel<<<NT / 8, 256>>>(p_y, p_yh);

    // y_inner = y @ s2i_w + s2i_b (fp16, K=64); then (+D*xmain)*sigmoid(gate)
    hgemm_kernel<<<dim3(INNER / 128, 32), 256>>>(p_yh, p_s2iT, s2i_b, p_yin, nullptr,
        NT, INNER, DSTATE, nullptr, nullptr, 0, nullptr, nullptr, nullptr, nullptr);
    skipgate_kernel<<<(NT * INNER) / 256, 256>>>(p_yin, p_xmain, p_xz, D_param, p_yinh);

    // x_mid = x + y_inner @ out_w + out_b
    hgemm_kernel<<<dim3(8, 32), 256>>>(p_yinh, p_woutT, out_b, p_xmid, nullptr,
        NT, DMODEL, INNER, nullptr, nullptr, 3, x, nullptr, nullptr, nullptr);

    // x2 = rmsnorm(x_mid)*norm2_w (fp32 for gating + half for fc1); out = x_mid
    rmsnorm_kernel<<<NT, 256>>>(p_xmid, norm2_w, p_x2, p_x2h, out);

    // gating: top-2 routing + per-expert compaction
    zero_cnt_kernel<<<1, 32>>>();
    gating_kernel<<<NT / 8, 256>>>(p_x2, gate_w, gate_b);

    // sparse MoE: gathered fc1(gelu)->half then fc2 scatter-accumulate
    for (int e = 0; e < NEXP; e++) {
        hgemm_kernel<<<dim3(32, 32), 256>>>(p_x2h,
            p_we1T + (size_t)e * NHID * DMODEL, e_b1 + (size_t)e * NHID, nullptr, p_hidh,
            NT, NHID, DMODEL, p_idx + e * NT, p_cnt + e, 2,
            nullptr, nullptr, nullptr, nullptr);
        hgemm_kernel<<<dim3(8, 32), 256>>>(p_hidh,
            p_we2T + (size_t)e * DMODEL * NHID, e_b2 + (size_t)e * DMODEL, nullptr, nullptr,
            NT, DMODEL, NHID, nullptr, p_cnt + e, 4,
            nullptr, p_idx + e * NT, p_wtok + e * NT, out);
    }
}

// round 16
// speedup vs baseline: 1.2520x; 1.2520x over previous
#include <cuda_runtime.h>
#include <cuda_fp16.h>
#include <cstdint>

// ---------------- problem constants ----------------
#define NT     4096          // B*T tokens
#define TTT    2048          // T per batch
#define DMODEL 1024
#define INNER  2048
#define DSTATE 64
#define NHID   4096
#define NEXP   4

// ---------------- device scratch ----------------
__device__ __half g_x1h[(size_t)NT * DMODEL];
__device__ float  g_xz[(size_t)NT * 4096];
__device__ float  g_xmain[(size_t)NT * INNER];
__device__ float  g_wdtbc[(size_t)INNER * 192];
__device__ float  g_bdtbc[192];
__device__ float  g_dtBC[(size_t)NT * 192];
__device__ float  g_y[(size_t)NT * DSTATE];
__device__ float  g_yin[(size_t)NT * INNER];
__device__ __half g_yinh[(size_t)NT * INNER];
__device__ float  g_xmid[(size_t)NT * DMODEL];
__device__ float  g_x2[(size_t)NT * DMODEL];
__device__ __half g_x2h[(size_t)NT * DMODEL];
__device__ __half g_hidh[(size_t)NT * NHID];
__device__ int    g_cnt[NEXP];
__device__ int    g_idx[NEXP * NT];
__device__ float  g_wtok[NEXP * NT];
// fp16 transposed weights [N, K]
__device__ __half g_winT[(size_t)4096 * DMODEL];
__device__ __half g_woutT[(size_t)DMODEL * INNER];
__device__ __half g_we1T[(size_t)NEXP * NHID * DMODEL];
__device__ __half g_we2T[(size_t)NEXP * DMODEL * NHID];

#define MMA_F16(d, a, b)                                                     \
    asm volatile("mma.sync.aligned.m16n8k16.row.col.f32.f16.f16.f32 "        \
                 "{%0,%1,%2,%3},{%4,%5,%6,%7},{%8,%9},{%0,%1,%2,%3};"        \
                 : "+f"(d[0]), "+f"(d[1]), "+f"(d[2]), "+f"(d[3])            \
                 : "r"(a[0]), "r"(a[1]), "r"(a[2]), "r"(a[3]),               \
                   "r"(b[0]), "r"(b[1]))

#define LDSM4(r0, r1, r2, r3, a)                                             \
    asm volatile("ldmatrix.sync.aligned.m8n8.x4.shared.b16 {%0,%1,%2,%3}, [%4];" \
                 : "=r"(r0), "=r"(r1), "=r"(r2), "=r"(r3) : "r"(a))

__device__ __forceinline__ uint32_t smem_u32(const void* p) {
    uint32_t a;
    asm("{ .reg .u64 t; cvta.to.shared.u64 t, %1; cvt.u32.u64 %0, t; }" : "=r"(a) : "l"(p));
    return a;
}

#define AP 12   // u32 pitch per 128-row tile row (8 u32 payload + 4 pad)

// ============ fp16 tensor-core GEMM: A[M,K] half, Bt[N,K] half =============
// epi: 0 = out = acc + bias
//      2 = out = gelu(acc + bias)          (exact erf)
//      3 = out = resid + acc + bias        (fp32 C only)
//      4 = moe_out[out_idx[r]] += wrow[r] * (acc + bias)
// Output: C (fp32) if Ch == null, else Ch (fp16).
// Requires: K % 16 == 0, N % 128 == 0.
__global__ __launch_bounds__(256, 2)
void hgemm_kernel(const __half* __restrict__ A, const __half* __restrict__ Bt,
                  const float* __restrict__ bias, float* __restrict__ C,
                  __half* __restrict__ Ch,
                  int M, int N, int K,
                  const int* __restrict__ a_idx, const int* __restrict__ Mdev,
                  int epi, const float* __restrict__ resid,
                  const int* __restrict__ out_idx, const float* __restrict__ wrow,
                  float* __restrict__ moe_out)
{
    if (Mdev) M = *Mdev;
    const int tileM = blockIdx.y * 128;
    const int tileN = blockIdx.x * 128;
    if (tileM >= M) return;

    __shared__ uint32_t As[2][128 * AP];
    __shared__ uint32_t Bs[2][128 * AP];

    const int tid  = threadIdx.x;
    const int lane = tid & 31;
    const int wid  = tid >> 5;
    const int wm   = wid >> 2;       // 0..1  (64-row band)
    const int wn   = wid & 3;        // 0..3  (32-col band)
    const int g    = lane >> 2;      // 0..7
    const int th   = lane & 3;       // 0..3

    // ---- staging assignments (identical pattern for A and B) ----
    const int s_row = tid >> 1;          // 0..127
    const int s_kh  = (tid & 1);         // half-row: 8 halves each
    const __half* a_ptr = nullptr;
    {
        int ar = tileM + s_row;
        if (ar < M) {
            int gi = a_idx ? a_idx[ar] : ar;
            a_ptr = A + (size_t)gi * K + s_kh * 8;
        }
    }
    const __half* b_ptr = Bt + (size_t)(tileN + s_row) * K + s_kh * 8;
    const uint32_t s_off = (uint32_t)(s_row * AP + s_kh * 4);

    // ---- ldmatrix per-lane offsets (u32 units) ----
    const uint32_t aoff = (uint32_t)(((lane & 7) + 8 * ((lane >> 3) & 1)) * AP + 4 * (lane >> 4));
    const uint32_t boff = (uint32_t)(((lane & 7) + 8 * (lane >> 4)) * AP + 4 * ((lane >> 3) & 1));
    const uint32_t As_base[2] = { smem_u32(&As[0][0]), smem_u32(&As[1][0]) };
    const uint32_t Bs_base[2] = { smem_u32(&Bs[0][0]), smem_u32(&Bs[1][0]) };

    float acc[4][4][4];
#pragma unroll
    for (int mt = 0; mt < 4; mt++)
#pragma unroll
        for (int nt = 0; nt < 4; nt++)
#pragma unroll
            for (int r = 0; r < 4; r++) acc[mt][nt][r] = 0.f;

    uint4 av = make_uint4(0u, 0u, 0u, 0u), bv;
    if (a_ptr) av = *(const uint4*)(a_ptr);
    bv = *(const uint4*)(b_ptr);
    *(uint4*)&As[0][s_off] = av;
    *(uint4*)&Bs[0][s_off] = bv;
    __syncthreads();

    const int KT = K >> 4;
    for (int kt = 0; kt < KT; kt++) {
        const int p = kt & 1;
        if (kt + 1 < KT) {       // prefetch next K-tile into regs
            const int k0 = (kt + 1) << 4;
            if (a_ptr) av = *(const uint4*)(a_ptr + k0);
            bv = *(const uint4*)(b_ptr + k0);
        }

        // ---- compute from stage p ----
        {
            uint32_t afr[4][4], bfr[4][2];
#pragma unroll
            for (int mt = 0; mt < 4; mt++) {
                const uint32_t addr = As_base[p] + ((uint32_t)((wm * 64 + mt * 16) * AP) + aoff) * 4u;
                LDSM4(afr[mt][0], afr[mt][1], afr[mt][2], afr[mt][3], addr);
            }
#pragma unroll
            for (int p2 = 0; p2 < 2; p2++) {
                const uint32_t addr = Bs_base[p] + ((uint32_t)((wn * 32 + p2 * 16) * AP) + boff) * 4u;
                LDSM4(bfr[2 * p2][0], bfr[2 * p2][1], bfr[2 * p2 + 1][0], bfr[2 * p2 + 1][1], addr);
            }
#pragma unroll
            for (int mt = 0; mt < 4; mt++)
#pragma unroll
                for (int nt = 0; nt < 4; nt++)
                    MMA_F16(acc[mt][nt], afr[mt], bfr[nt]);
        }

        if (kt + 1 < KT) {       // store next stage
            const int q = p ^ 1;
            *(uint4*)&As[q][s_off] = av;
            *(uint4*)&Bs[q][s_off] = bv;
        }
        __syncthreads();
    }

    // ---- epilogue ----
#pragma unroll
    for (int mt = 0; mt < 4; mt++) {
        const int rbase = tileM + wm * 64 + mt * 16 + g;
#pragma unroll
        for (int h = 0; h < 2; h++) {
            const int r = rbase + h * 8;
            if (r >= M) continue;
            int   orow = r;
            float wr   = 1.f;
            if (epi == 4) { orow = out_idx[r]; wr = wrow[r]; }
#pragma unroll
            for (int nt = 0; nt < 4; nt++) {
                const int c = tileN + wn * 32 + nt * 8 + 2 * th;
                float v0 = acc[mt][nt][h * 2 + 0] + bias[c];
                float v1 = acc[mt][nt][h * 2 + 1] + bias[c + 1];
                if (epi == 2) {
                    v0 = 0.5f * v0 * (1.f + erff(v0 * 0.70710678118654752f));
                    v1 = 0.5f * v1 * (1.f + erff(v1 * 0.70710678118654752f));
                }
                if (epi == 3) {
                    v0 += resid[(size_t)r * N + c];
                    v1 += resid[(size_t)r * N + c + 1];
                }
                if (epi == 4) {
                    float* p2 = moe_out + (size_t)orow * N + c;
                    p2[0] += wr * v0;
                    p2[1] += wr * v1;
                } else if (Ch) {
                    __half2 hv = __floats2half2_rn(v0, v1);
                    *(__half2*)(Ch + (size_t)r * N + c) = hv;
                } else {
                    C[(size_t)r * N + c]     = v0;
                    C[(size_t)r * N + c + 1] = v1;
                }
            }
        }
    }
}

// ---------------- weight transpose+convert: W[K,N] f32 -> Wt[N,K] f16 ------
__global__ void wT_kernel(const float* __restrict__ W, __half* __restrict__ Wt,
                          int K, int N)
{
    __shared__ float t[32][33];
    const int n0 = blockIdx.x * 32, k0 = blockIdx.y * 32;
    const int x = threadIdx.x, y = threadIdx.y;
#pragma unroll
    for (int j = 0; j < 32; j += 8)
        t[y + j][x] = W[(size_t)(k0 + y + j) * N + n0 + x];
    __syncthreads();
#pragma unroll
    for (int j = 0; j < 32; j += 8)
        Wt[(size_t)(n0 + y + j) * K + k0 + x] = __float2half(t[x][y + j]);
}

// ---------------- generic fp32 SGEMM (small/precision-sensitive GEMMs) -----
__global__ __launch_bounds__(256, 2)
void sgemm_kernel(const float* __restrict__ A, const float* __restrict__ B,
                  const float* __restrict__ bias, float* __restrict__ C,
                  int M, int N, int K)
{
    const int tileM = blockIdx.y * 128;
    const int tileN = blockIdx.x * 128;
    if (tileM >= M) return;

    __shared__ float As[8][128];
    __shared__ float Bs[8][128];

    const int tid = threadIdx.x;
    const int a_r = tid >> 1;
    const int a_k = (tid & 1) * 4;
    const int b_k = tid >> 5;
    const int b_c = (tid & 31) * 4;
    const int ty  = tid >> 4;
    const int tx  = tid & 15;

    const float* a_ptr = nullptr;
    if (tileM + a_r < M) a_ptr = A + (size_t)(tileM + a_r) * K + a_k;
    const bool   b_ok  = (tileN + b_c) < N;
    const float* b_ptr = B + (size_t)b_k * N + tileN + b_c;

    float acc[8][8];
#pragma unroll
    for (int i = 0; i < 8; i++)
#pragma unroll
        for (int j = 0; j < 8; j++) acc[i][j] = 0.f;

    float4 av = make_float4(0.f,0.f,0.f,0.f);
    float4 bv = make_float4(0.f,0.f,0.f,0.f);
    if (a_ptr) av = *(const float4*)(a_ptr);
    if (b_ok)  bv = *(const float4*)(b_ptr);

    for (int k0 = 0; k0 < K; k0 += 8) {
        As[a_k + 0][a_r] = av.x; As[a_k + 1][a_r] = av.y;
        As[a_k + 2][a_r] = av.z; As[a_k + 3][a_r] = av.w;
        *(float4*)&Bs[b_k][b_c] = bv;
        __syncthreads();

        if (k0 + 8 < K) {
            av = make_float4(0.f,0.f,0.f,0.f);
            bv = make_float4(0.f,0.f,0.f,0.f);
            if (a_ptr) av = *(const float4*)(a_ptr + k0 + 8);
            if (b_ok)  bv = *(const float4*)(b_ptr + (size_t)(k0 + 8) * N);
        }

#pragma unroll
        for (int kk = 0; kk < 8; kk++) {
            float4 ra0 = *(const float4*)&As[kk][ty * 8];
            float4 ra1 = *(const float4*)&As[kk][ty * 8 + 4];
            float4 rb0 = *(const float4*)&Bs[kk][tx * 8];
            float4 rb1 = *(const float4*)&Bs[kk][tx * 8 + 4];
            float ra[8] = {ra0.x, ra0.y, ra0.z, ra0.w, ra1.x, ra1.y, ra1.z, ra1.w};
            float rb[8] = {rb0.x, rb0.y, rb0.z, rb0.w, rb1.x, rb1.y, rb1.z, rb1.w};
#pragma unroll
            for (int i = 0; i < 8; i++)
#pragma unroll
                for (int j = 0; j < 8; j++)
                    acc[i][j] = fmaf(ra[i], rb[j], acc[i][j]);
        }
        __syncthreads();
    }

    const int row0 = tileM + ty * 8;
    const int col0 = tileN + tx * 8;
#pragma unroll
    for (int i = 0; i < 8; i++) {
        int r = row0 + i;
        if (r >= M) break;
#pragma unroll
        for (int j = 0; j < 8; j++) {
            int c = col0 + j;
            if (c >= N) continue;
            C[(size_t)r * N + c] = acc[i][j] + bias[c];
        }
    }
}

// -------- RMSNorm, vectorized: 256 threads x float4 covers D=1024 ---------
__global__ void rmsnorm_kernel(const float* __restrict__ in,
                               const float* __restrict__ w,
                               float* __restrict__ out,
                               __half* __restrict__ out_h,
                               float* __restrict__ copy_dst)
{
    const int tok = blockIdx.x;
    const int tid = threadIdx.x;
    const float4 v = ((const float4*)(in + (size_t)tok * DMODEL))[tid];
    float s = v.x * v.x + v.y * v.y + v.z * v.z + v.w * v.w;
    __shared__ float red[8];
    for (int off = 16; off; off >>= 1) s += __shfl_xor_sync(0xffffffffu, s, off);
    if ((tid & 31) == 0) red[tid >> 5] = s;
    __syncthreads();
    if (tid < 32) {
        float tv = (tid < 8) ? red[tid] : 0.f;
        for (int off = 4; off; off >>= 1) tv += __shfl_xor_sync(0xffffffffu, tv, off);
        if (tid == 0) red[0] = tv;
    }
    __syncthreads();
    const float nr = rsqrtf(red[0] * (1.f / DMODEL) + 1e-6f);
    const float4 wv = ((const float4*)w)[tid];
    float4 o;
    o.x = v.x * nr * wv.x; o.y = v.y * nr * wv.y;
    o.z = v.z * nr * wv.z; o.w = v.w * nr * wv.w;
    if (out) ((float4*)(out + (size_t)tok * DMODEL))[tid] = o;
    if (out_h) {
        __half2 h0 = __floats2half2_rn(o.x, o.y);
        __half2 h1 = __floats2half2_rn(o.z, o.w);
        uint2 u = make_uint2(*(uint32_t*)&h0, *(uint32_t*)&h1);
        ((uint2*)(out_h + (size_t)tok * DMODEL))[tid] = u;
    }
    if (copy_dst) ((float4*)(copy_dst + (size_t)tok * DMODEL))[tid] = v;
}

// ----- causal depthwise conv (K=3) + bias + SiLU, 4 channels/thread -------
__global__ void conv_silu_kernel(const float* __restrict__ xz,
                                 const float* __restrict__ cw,
                                 const float* __restrict__ cb,
                                 float* __restrict__ xmain,
                                 __half* __restrict__ xmainh)
{
    const int idx = blockIdx.x * 256 + threadIdx.x;   // NT*INNER/4 threads
    const int e   = idx * 4;
    const int c   = e & (INNER - 1);
    const int tok = e >> 11;
    const int t   = tok & (TTT - 1);
    const float4 x0 = *(const float4*)(xz + (size_t)tok * 4096 + c);
    float4 x1 = make_float4(0.f, 0.f, 0.f, 0.f), x2 = x1;
    if (t >= 1) x1 = *(const float4*)(xz + (size_t)(tok - 1) * 4096 + c);
    if (t >= 2) x2 = *(const float4*)(xz + (size_t)(tok - 2) * 4096 + c);
    float4 o;
    {
        float vv[4];
        const float xm2[4] = {x2.x, x2.y, x2.z, x2.w};
        const float xm1[4] = {x1.x, x1.y, x1.z, x1.w};
        const float xm0[4] = {x0.x, x0.y, x0.z, x0.w};
#pragma unroll
        for (int j = 0; j < 4; j++) {
            const int ch = c + j;
            float v = cb[ch];
            v = fmaf(cw[ch * 3 + 0], xm2[j],
                fmaf(cw[ch * 3 + 1], xm1[j],
                fmaf(cw[ch * 3 + 2], xm0[j], v)));
            vv[j] = v / (1.f + expf(-v));
        }
        o = make_float4(vv[0], vv[1], vv[2], vv[3]);
    }
    *(float4*)(xmain + e) = o;
    if (xmainh) {
        __half2 h0 = __floats2half2_rn(o.x, o.y);
        __half2 h1 = __floats2half2_rn(o.z, o.w);
        *(uint2*)(xmainh + e) = make_uint2(*(uint32_t*)&h0, *(uint32_t*)&h1);
    }
}

// ---------------- pack dt_w|bp_w|cp_w into [2048,192] (and biases) --------
__global__ void pack_dtbc_kernel(const float* __restrict__ dtw, const float* __restrict__ bpw,
                                 const float* __restrict__ cpw, const float* __restrict__ dtb,
                                 const float* __restrict__ bpb, const float* __restrict__ cpb)
{
    const int i = blockIdx.x * 256 + threadIdx.x;
    if (i < INNER * 192) {
        int r = i / 192, c = i % 192;
        int sel = c >> 6, cc = c & 63;
        const float* w = (sel == 0) ? dtw : (sel == 1) ? bpw : cpw;
        g_wdtbc[i] = w[r * 64 + cc];
    }
    if (i < 192) {
        int sel = i >> 6, cc = i & 63;
        const float* b = (sel == 0) ? dtb : (sel == 1) ? bpb : cpb;
        g_bdtbc[i] = b[cc];
    }
}

// ---------------- selective-state scan: warp per (batch, state) chain ------
__global__ void scan_kernel(const float* __restrict__ dtBC, float* __restrict__ y)
{
    const int warp = blockIdx.x;            // 128 chains, one warp per block
    const int lane = threadIdx.x & 31;
    const int b = warp >> 6, s = warp & 63;
    const int t0 = lane * 64;
    const size_t base = (size_t)b * TTT * 192;

    float A = 1.f, Bc = 0.f;
    for (int t = t0; t < t0 + 64; t++) {
        size_t o = base + (size_t)t * 192;
        float dt = 1.f / (1.f + expf(-dtBC[o + s]));
        float bvv = dtBC[o + 64 + s];
        float a = 1.f - dt;
        Bc = fmaf(a, Bc, dt * bvv);
        A *= a;
    }
    for (int off = 1; off < 32; off <<= 1) {
        float Au = __shfl_up_sync(0xffffffffu, A, off);
        float Bu = __shfl_up_sync(0xffffffffu, Bc, off);
        if (lane >= off) { Bc = fmaf(A, Bu, Bc); A = A * Au; }
    }
    float start = __shfl_up_sync(0xffffffffu, Bc, 1);
    if (lane == 0) start = 0.f;

    float st = start;
    for (int t = t0; t < t0 + 64; t++) {
        size_t o = base + (size_t)t * 192;
        float dt = 1.f / (1.f + expf(-dtBC[o + s]));
        float bvv = dtBC[o + 64 + s];
        float cv = dtBC[o + 128 + s];
        st = fmaf(1.f - dt, st, dt * bvv);
        y[((size_t)b * TTT + t) * 64 + s] = cv * st;
    }
}

// ---------------- LayerNorm over 64 dims (warp per token, no weight) -------
__global__ void ln64_kernel(float* __restrict__ y)
{
    const int token = blockIdx.x * 8 + (threadIdx.x >> 5);
    const int lane  = threadIdx.x & 31;
    float* row = y + (size_t)token * 64;
    float a = row[lane], b = row[lane + 32];
    float s = a + b;
    for (int off = 16; off; off >>= 1) s += __shfl_xor_sync(0xffffffffu, s, off);
    float mu = s * (1.f / 64.f);
    float da = a - mu, db = b - mu;
    float v = da * da + db * db;
    for (int off = 16; off; off >>= 1) v += __shfl_xor_sync(0xffffffffu, v, off);
    float inv = rsqrtf(v * (1.f / 64.f) + 1e-5f);
    row[lane] = da * inv;
    row[lane + 32] = db * inv;
}

// -------- yinh = half((yin + D*xmain) * sigmoid(gate)), 4 elems/thread -----
__global__ void skipgate_kernel(const float* __restrict__ yin, const float* __restrict__ xmain,
                                const float* __restrict__ xz, const float* __restrict__ Dp,
                                __half* __restrict__ yinh)
{
    const int idx = blockIdx.x * 256 + threadIdx.x;   // NT*INNER/4
    const int e   = idx * 4;
    const int c   = e & (INNER - 1);
    const int tok = e >> 11;
    const float4 gv = *(const float4*)(xz + (size_t)tok * 4096 + INNER + c);
    const float4 yv = *(const float4*)(yin + e);
    const float4 xv = *(const float4*)(xmain + e);
    const float4 dv = *(const float4*)(Dp + c);
    float o0 = fmaf(dv.x, xv.x, yv.x) / (1.f + expf(-gv.x));
    float o1 = fmaf(dv.y, xv.y, yv.y) / (1.f + expf(-gv.y));
    float o2 = fmaf(dv.z, xv.z, yv.z) / (1.f + expf(-gv.z));
    float o3 = fmaf(dv.w, xv.w, yv.w) / (1.f + expf(-gv.w));
    __half2 h0 = __floats2half2_rn(o0, o1);
    __half2 h1 = __floats2half2_rn(o2, o3);
    *(uint2*)(yinh + e) = make_uint2(*(uint32_t*)&h0, *(uint32_t*)&h1);
}

// ---------------- gating: logits, top-2, softmax, expert compaction --------
__global__ void zero_cnt_kernel() { if (threadIdx.x < NEXP) g_cnt[threadIdx.x] = 0; }

__global__ void gating_kernel(const float* __restrict__ x2, const float* __restrict__ gw,
                              const float* __restrict__ gb)
{
    const int token = blockIdx.x * 8 + (threadIdx.x >> 5);
    const int lane  = threadIdx.x & 31;
    const float* row = x2 + (size_t)token * DMODEL;
    float a0 = 0.f, a1 = 0.f, a2 = 0.f, a3 = 0.f;
    for (int d = lane; d < DMODEL; d += 32) {
        float xv = row[d];
        float4 g = *(const float4*)(gw + d * 4);
        a0 = fmaf(xv, g.x, a0); a1 = fmaf(xv, g.y, a1);
        a2 = fmaf(xv, g.z, a2); a3 = fmaf(xv, g.w, a3);
    }
    for (int off = 16; off; off >>= 1) {
        a0 += __shfl_xor_sync(0xffffffffu, a0, off);
        a1 += __shfl_xor_sync(0xffffffffu, a1, off);
        a2 += __shfl_xor_sync(0xffffffffu, a2, off);
        a3 += __shfl_xor_sync(0xffffffffu, a3, off);
    }
    if (lane == 0) {
        float lg[4] = {a0 + gb[0], a1 + gb[1], a2 + gb[2], a3 + gb[3]};
        int i1 = 0;
        for (int e = 1; e < 4; e++) if (lg[e] > lg[i1]) i1 = e;
        int i2 = -1;
        for (int e = 0; e < 4; e++) if (e != i1 && (i2 < 0 || lg[e] > lg[i2])) i2 = e;
        float t  = expf(lg[i2] - lg[i1]);
        float p1 = 1.f / (1.f + t);
        float p2 = t / (1.f + t);
        int p = atomicAdd(&g_cnt[i1], 1); g_idx[i1 * NT + p] = token; g_wtok[i1 * NT + p] = p1;
        int q = atomicAdd(&g_cnt[i2], 1); g_idx[i2 * NT + q] = token; g_wtok[i2 * NT + q] = p2;
    }
}

// ---------------- host orchestration ----------------
extern "C" void kernel_launch(void* const* d_in, const int* in_sizes, int n_in,
                              void* d_out, int out_size)
{
    const float* x         = (const float*)d_in[0];
    const float* norm1_w   = (const float*)d_in[1];
    const float* norm2_w   = (const float*)d_in[2];
    const float* in_proj_w = (const float*)d_in[3];
    const float* in_proj_b = (const float*)d_in[4];
    const float* conv_w    = (const float*)d_in[5];
    const float* conv_b    = (const float*)d_in[6];
    const float* dt_w      = (const float*)d_in[7];
    const float* dt_b      = (const float*)d_in[8];
    const float* bp_w      = (const float*)d_in[9];
    const float* bp_b      = (const float*)d_in[10];
    const float* cp_w      = (const float*)d_in[11];
    const float* cp_b      = (const float*)d_in[12];
    const float* s2i_w     = (const float*)d_in[13];
    const float* s2i_b     = (const float*)d_in[14];
    const float* D_param   = (const float*)d_in[15];
    const float* out_w     = (const float*)d_in[16];
    const float* out_b     = (const float*)d_in[17];
    const float* gate_w    = (const float*)d_in[18];
    const float* gate_b    = (const float*)d_in[19];
    const float* e_w1      = (const float*)d_in[20];
    const float* e_b1      = (const float*)d_in[21];
    const float* e_w2      = (const float*)d_in[22];
    const float* e_b2      = (const float*)d_in[23];
    float* out = (float*)d_out;

    float *p_xz, *p_xmain, *p_wdtbc, *p_bdtbc, *p_dtBC, *p_y, *p_yin,
          *p_xmid, *p_x2, *p_wtok;
    __half *p_x1h, *p_yinh, *p_x2h, *p_hidh, *p_winT, *p_woutT, *p_we1T, *p_we2T;
    int *p_cnt, *p_idx;
    cudaGetSymbolAddress((void**)&p_x1h, g_x1h);
    cudaGetSymbolAddress((void**)&p_xz, g_xz);
    cudaGetSymbolAddress((void**)&p_xmain, g_xmain);
    cudaGetSymbolAddress((void**)&p_wdtbc, g_wdtbc);
    cudaGetSymbolAddress((void**)&p_bdtbc, g_bdtbc);
    cudaGetSymbolAddress((void**)&p_dtBC, g_dtBC);
    cudaGetSymbolAddress((void**)&p_y, g_y);
    cudaGetSymbolAddress((void**)&p_yin, g_yin);
    cudaGetSymbolAddress((void**)&p_yinh, g_yinh);
    cudaGetSymbolAddress((void**)&p_xmid, g_xmid);
    cudaGetSymbolAddress((void**)&p_x2, g_x2);
    cudaGetSymbolAddress((void**)&p_x2h, g_x2h);
    cudaGetSymbolAddress((void**)&p_hidh, g_hidh);
    cudaGetSymbolAddress((void**)&p_cnt, g_cnt);
    cudaGetSymbolAddress((void**)&p_idx, g_idx);
    cudaGetSymbolAddress((void**)&p_wtok, g_wtok);
    cudaGetSymbolAddress((void**)&p_winT, g_winT);
    cudaGetSymbolAddress((void**)&p_woutT, g_woutT);
    cudaGetSymbolAddress((void**)&p_we1T, g_we1T);
    cudaGetSymbolAddress((void**)&p_we2T, g_we2T);

    const dim3 tb(32, 8);

    // launches 1..5 chosen so #6 = the big in_proj hgemm (ncu -s 5 -c 1 target)
    wT_kernel<<<dim3(4096 / 32, DMODEL / 32), tb>>>(in_proj_w, p_winT, DMODEL, 4096);   // 1
    rmsnorm_kernel<<<NT, 256>>>(x, norm1_w, nullptr, p_x1h, nullptr);                   // 2
    wT_kernel<<<dim3(DMODEL / 32, INNER / 32), tb>>>(out_w, p_woutT, INNER, DMODEL);    // 3
    wT_kernel<<<dim3(NHID / 32, DMODEL / 32), tb>>>(e_w1, p_we1T, DMODEL, NHID);        // 4
    wT_kernel<<<dim3(DMODEL / 32, NHID / 32), tb>>>(e_w2, p_we2T, NHID, DMODEL);        // 5

    // 6) xz = x1 @ in_proj_w + b   [4096 x 4096]  <-- ncu capture target
    hgemm_kernel<<<dim3(32, 32), 256>>>(p_x1h, p_winT, in_proj_b, p_xz, nullptr,
        NT, 4096, DMODEL, nullptr, nullptr, 0, nullptr, nullptr, nullptr, nullptr);

    // remaining expert weight transposes (experts 1..3)
    for (int e = 1; e < NEXP; e++) {
        wT_kernel<<<dim3(NHID / 32, DMODEL / 32), tb>>>(
            e_w1 + (size_t)e * DMODEL * NHID, p_we1T + (size_t)e * NHID * DMODEL, DMODEL, NHID);
        wT_kernel<<<dim3(DMODEL / 32, NHID / 32), tb>>>(
            e_w2 + (size_t)e * NHID * DMODEL, p_we2T + (size_t)e * DMODEL * NHID, NHID, DMODEL);
    }

    // x_main = silu(causal depthwise conv(xz[:, :2048]) + conv_b)  (fp32 only)
    conv_silu_kernel<<<(NT * INNER) / 1024, 256>>>(p_xz, conv_w, conv_b, p_xmain, nullptr);

    // packed [dt|B|C] projection (fp32: feeds the recurrence)
    pack_dtbc_kernel<<<(INNER * 192 + 255) / 256, 256>>>(dt_w, bp_w, cp_w, dt_b, bp_b, cp_b);
    sgemm_kernel<<<dim3(2, 32), 256>>>(p_xmain, p_wdtbc, p_bdtbc, p_dtBC,
        NT, 192, INNER);

    // selective scan + LayerNorm(64)
    scan_kernel<<<128, 32>>>(p_dtBC, p_y);
    ln64_kernel<<<NT / 8, 256>>>(p_y);

    // y_inner = y @ s2i_w + s2i_b (fp32, K=64) ; then (+D*xmain)*sigmoid(gate)
    sgemm_kernel<<<dim3(16, 32), 256>>>(p_y, s2i_w, s2i_b, p_yin,
        NT, INNER, DSTATE);
    skipgate_kernel<<<(NT * INNER) / 1024, 256>>>(p_yin, p_xmain, p_xz, D_param, p_yinh);

    // x_mid = x + y_inner @ out_w + out_b
    hgemm_kernel<<<dim3(8, 32), 256>>>(p_yinh, p_woutT, out_b, p_xmid, nullptr,
        NT, DMODEL, INNER, nullptr, nullptr, 3, x, nullptr, nullptr, nullptr);

    // x2 = rmsnorm(x_mid)*norm2_w (fp32 for gating + half for fc1); out = x_mid
    rmsnorm_kernel<<<NT, 256>>>(p_xmid, norm2_w, p_x2, p_x2h, out);

    // gating: top-2 routing + per-expert compaction
    zero_cnt_kernel<<<1, 32>>>();
    gating_kernel<<<NT / 8, 256>>>(p_x2, gate_w, gate_b);

    // sparse MoE: gathered fc1(gelu)->half then fc2 scatter-accumulate
    for (int e = 0; e < NEXP; e++) {
        hgemm_kernel<<<dim3(32, 32), 256>>>(p_x2h,
            p_we1T + (size_t)e * NHID * DMODEL, e_b1 + (size_t)e * NHID, nullptr, p_hidh,
            NT, NHID, DMODEL, p_idx + e * NT, p_cnt + e, 2,
            nullptr, nullptr, nullptr, nullptr);
        hgemm_kernel<<<dim3(8, 32), 256>>>(p_hidh,
            p_we2T + (size_t)e * DMODEL * NHID, e_b2 + (size_t)e * DMODEL, nullptr, nullptr,
            NT, DMODEL, NHID, nullptr, p_cnt + e, 4,
            nullptr, p_idx + e * NT, p_wtok + e * NT, out);
    }
}